// round 16
// baseline (speedup 1.0000x reference)
#include <cuda_runtime.h>
#include <cstdint>

#define NPTS 30000
#define NHALF 15000
#define CDIM 128
#define HEADS 8
#define DHEAD 16
#define SNBR 16
#define OSDIM 16
#define EPSV 1e-5f

typedef unsigned long long u64;

// packed f32x2 helpers (FFMA2 path — PTX-only on sm_103a)
#define F32X2_FMA(d, a, b, c) \
    asm("fma.rn.f32x2 %0, %1, %2, %3;" : "=l"(d) : "l"(a), "l"(b), "l"(c))
#define F32X2_ADD(d, a, b) \
    asm("add.rn.f32x2 %0, %1, %2;" : "=l"(d) : "l"(a), "l"(b))
#define F32X2_MUL(d, a, b) \
    asm("mul.rn.f32x2 %0, %1, %2;" : "=l"(d) : "l"(a), "l"(b))

__device__ __forceinline__ u64 pack2(float lo, float hi) {
    u64 r; asm("mov.b64 %0, {%1, %2};" : "=l"(r) : "f"(lo), "f"(hi)); return r;
}
__device__ __forceinline__ u64 dup2(float x) {
    u64 r; asm("mov.b64 %0, {%1, %1};" : "=l"(r) : "f"(x)); return r;
}
__device__ __forceinline__ float2 unpack2(u64 v) {
    float lo, hi; asm("mov.b64 {%0, %1}, %2;" : "=f"(lo), "=f"(hi) : "l"(v));
    return make_float2(lo, hi);
}
__device__ __forceinline__ u64 relu2(u64 x) {
    float2 f = unpack2(x);
    return pack2(fmaxf(f.x, 0.f), fmaxf(f.y, 0.f));
}

#define NEG1P 0xBF800000BF800000ULL   // (-1.0f, -1.0f)

// tf32 helpers
__device__ __forceinline__ uint32_t f2tf(float f) {
    uint32_t r; asm("cvt.rna.tf32.f32 %0, %1;" : "=r"(r) : "f"(f)); return r;
}
#define MMA_TF32(c, a, b) \
    asm("mma.sync.aligned.m16n8k8.row.col.f32.tf32.tf32.f32 " \
        "{%0,%1,%2,%3}, {%4,%5,%6,%7}, {%8,%9}, {%0,%1,%2,%3};" \
        : "+f"((c)[0]), "+f"((c)[1]), "+f"((c)[2]), "+f"((c)[3]) \
        : "r"((a)[0]), "r"((a)[1]), "r"((a)[2]), "r"((a)[3]), \
          "r"((b)[0]), "r"((b)[1]))

// ---------------------------------------------------------------------------
// Block-invariant parameters in the constant bank.
// ---------------------------------------------------------------------------
struct __align__(16) CParams {
    float Ww1[DHEAD * OSDIM];   // 256 (kept for layout stability; attn uses smem copy)
    float Wp2[3 * CDIM];        // 384
    float bp2[CDIM];            // 128
    float gw1[DHEAD];
    float betaw1[DHEAD];
    float bw1[OSDIM];
    float gw2[OSDIM];
    float betaw2[OSDIM];
    float rs2[OSDIM];           // rowsum(Ww2)
    float Wp1[9], bp1[3], gp[3], betap[3];
    float bw2sum;               // sum(bw2)
};

__constant__ CParams c_par;
__device__   CParams g_stage;

// Scratch (device globals: no allocation allowed)
__device__ __align__(256) float g_xq[NPTS * CDIM];
__device__ __align__(256) float g_xk[NPTS * CDIM];
__device__ __align__(256) float g_xv[NPTS * CDIM];

// ---------------------------------------------------------------------------
// Kernel 0: pack block-invariant params into g_stage (then D2D -> c_par).
// ---------------------------------------------------------------------------
__global__ void stage_kernel(const float* __restrict__ Wp1, const float* __restrict__ bp1,
                             const float* __restrict__ gp,  const float* __restrict__ betap,
                             const float* __restrict__ Wp2, const float* __restrict__ bp2,
                             const float* __restrict__ gw1, const float* __restrict__ betaw1,
                             const float* __restrict__ Ww1, const float* __restrict__ bw1,
                             const float* __restrict__ gw2, const float* __restrict__ betaw2,
                             const float* __restrict__ Ww2, const float* __restrict__ bw2)
{
    int t = threadIdx.x;   // 384 threads
    if (t < 384) g_stage.Wp2[t] = Wp2[t];
    if (t < 256) g_stage.Ww1[t] = Ww1[t];
    if (t < 128) g_stage.bp2[t] = bp2[t];
    if (t < 16) {
        g_stage.gw1[t]    = gw1[t];
        g_stage.betaw1[t] = betaw1[t];
        g_stage.bw1[t]    = bw1[t];
        g_stage.gw2[t]    = gw2[t];
        g_stage.betaw2[t] = betaw2[t];
        float rs = 0.f;
#pragma unroll
        for (int o = 0; o < OSDIM; o++) rs += Ww2[t * OSDIM + o];
        g_stage.rs2[t] = rs;
    }
    if (t < 9) g_stage.Wp1[t] = Wp1[t];
    if (t < 3) {
        g_stage.bp1[t]   = bp1[t];
        g_stage.gp[t]    = gp[t];
        g_stage.betap[t] = betap[t];
    }
    if (t == 0) {
        float sb = 0.f;
#pragma unroll
        for (int o = 0; o < OSDIM; o++) sb += bw2[o];
        g_stage.bw2sum = sb;
    }
}

// ---------------------------------------------------------------------------
// Kernel 1: fused QKV GEMM on tensor cores — single-pass TF32 (proven).
// ---------------------------------------------------------------------------
#define GTM 128
#define GTN 64
#define GTK 32
#define AS_STR 36
#define BS_STR 72
#define GEMM_SMEM_WORDS (GTM * AS_STR + GTK * BS_STR)
#define GEMM_SMEM_BYTES (GEMM_SMEM_WORDS * 4)

__global__ __launch_bounds__(256, 2)
void qkv_gemm_tf32(const float* __restrict__ x,
                   const float* __restrict__ Wq, const float* __restrict__ bq,
                   const float* __restrict__ Wk, const float* __restrict__ bk,
                   const float* __restrict__ Wv, const float* __restrict__ bv,
                   int row_base, int row_end)
{
    const float* W; const float* bias; float* dst;
    if (blockIdx.z == 0)      { W = Wq; bias = bq; dst = g_xq; }
    else if (blockIdx.z == 1) { W = Wk; bias = bk; dst = g_xk; }
    else                      { W = Wv; bias = bv; dst = g_xv; }

    extern __shared__ uint32_t smem_u[];
    uint32_t* As = smem_u;
    uint32_t* Bs = As + GTM * AS_STR;

    const int tid  = threadIdx.x;
    const int wid  = tid >> 5;
    const int lane = tid & 31;
    const int g    = lane >> 2;
    const int tg   = lane & 3;

    const int warp_m = wid & 3;
    const int warp_n = wid >> 2;
    const int row0 = row_base + blockIdx.x * GTM;
    const int col0 = blockIdx.y * GTN;

    float c[2][4][4];
#pragma unroll
    for (int mt = 0; mt < 2; mt++)
#pragma unroll
        for (int nt = 0; nt < 4; nt++)
#pragma unroll
            for (int q = 0; q < 4; q++) c[mt][nt][q] = 0.f;

    const int arow_ = tid >> 3;
    const int ak4   = (tid & 7) * 4;
    const int brow_ = tid >> 4;
    const int bn4   = (tid & 15) * 4;

    for (int kk = 0; kk < CDIM; kk += GTK) {
        __syncthreads();

#pragma unroll
        for (int ps = 0; ps < 4; ps++) {
            int m  = arow_ + ps * 32;
            int gr = row0 + m;
            float4 v = (gr < row_end)
                     ? *(const float4*)(x + (size_t)gr * CDIM + kk + ak4)
                     : make_float4(0.f, 0.f, 0.f, 0.f);
            uint4 hi;
            hi.x = f2tf(v.x); hi.y = f2tf(v.y);
            hi.z = f2tf(v.z); hi.w = f2tf(v.w);
            *(uint4*)&As[m * AS_STR + ak4] = hi;
        }
#pragma unroll
        for (int ps = 0; ps < 2; ps++) {
            int k = brow_ + ps * 16;
            float4 v = *(const float4*)(W + (size_t)(kk + k) * CDIM + col0 + bn4);
            uint4 hi;
            hi.x = f2tf(v.x); hi.y = f2tf(v.y);
            hi.z = f2tf(v.z); hi.w = f2tf(v.w);
            *(uint4*)&Bs[k * BS_STR + bn4] = hi;
        }
        __syncthreads();

#pragma unroll
        for (int ks = 0; ks < 4; ks++) {
            const int k0 = ks * 8;
            uint32_t ah[2][4], bh[4][2];
#pragma unroll
            for (int mt = 0; mt < 2; mt++) {
                int rb = warp_m * 32 + mt * 16 + g;
                int o  = rb * AS_STR + k0 + tg;
                ah[mt][0] = As[o];
                ah[mt][1] = As[o + 8 * AS_STR];
                ah[mt][2] = As[o + 4];
                ah[mt][3] = As[o + 8 * AS_STR + 4];
            }
#pragma unroll
            for (int nt = 0; nt < 4; nt++) {
                int cb = warp_n * 32 + nt * 8 + g;
                int o  = (k0 + tg) * BS_STR + cb;
                bh[nt][0] = Bs[o];
                bh[nt][1] = Bs[o + 4 * BS_STR];
            }
#pragma unroll
            for (int mt = 0; mt < 2; mt++)
#pragma unroll
                for (int nt = 0; nt < 4; nt++)
                    MMA_TF32(c[mt][nt], ah[mt], bh[nt]);
        }
    }

#pragma unroll
    for (int nt = 0; nt < 4; nt++) {
        int cn = col0 + warp_n * 32 + nt * 8 + 2 * tg;
        float2 bb = *(const float2*)(bias + cn);
#pragma unroll
        for (int mt = 0; mt < 2; mt++) {
            int gr0 = row0 + warp_m * 32 + mt * 16 + g;
            if (gr0 < row_end) {
                float2 o0 = make_float2(c[mt][nt][0] + bb.x, c[mt][nt][1] + bb.y);
                *(float2*)(dst + (size_t)gr0 * CDIM + cn) = o0;
            }
            int gr1 = gr0 + 8;
            if (gr1 < row_end) {
                float2 o1 = make_float2(c[mt][nt][2] + bb.x, c[mt][nt][3] + bb.y);
                *(float2*)(dst + (size_t)gr1 * CDIM + cn) = o1;
            }
        }
    }
}

// ---------------------------------------------------------------------------
// Kernel 2: per-point fused attention. R15 base; the 16x16 Ww1 matmul is
// replaced by 8x mma.sync.m16n8k8.tf32 per warp (R=32x16 through a stride-20
// smem transpose buffer; result read back into the SAME per-lane layout, so
// LN2/softmax/V path are untouched).
// ---------------------------------------------------------------------------
__global__ __launch_bounds__(128)
void attn_kernel(const float* __restrict__ p,
                 const int*   __restrict__ idx,
                 const float* __restrict__ Ww1g,
                 const float* __restrict__ Wp2g,
                 const float* __restrict__ bp2g,
                 float* __restrict__ out,
                 int off)
{
    const int i   = blockIdx.x + off;
    const int tid = threadIdx.x;          // 0..127
    const int lane = tid & 31;

    __shared__ __align__(16) float skv[SNBR * CDIM];   // K gather, swizzled
    __shared__ __align__(16) float sW1s[16 * 17];      // Ww1 [k][n], pad 17
    __shared__ __align__(16) float srw[4 * 32 * 20];   // per-warp r/w1 buffer
    __shared__ int sidx[SNBR];

    if (tid < SNBR) sidx[tid] = idx[i * SNBR + tid];

    // stage Ww1 into smem (2 elems/thread)
#pragma unroll
    for (int e = tid; e < 256; e += 128)
        sW1s[(e >> 4) * 17 + (e & 15)] = __ldg(Ww1g + e);

    // --- gather K rows: warp-uniform row index via LDG, swizzled STS ---
    {
        const int warp = tid >> 5;
#pragma unroll
        for (int j = 0; j < 4; j++) {
            int sr  = warp * 4 + j;
            int row = __ldg(idx + i * SNBR + sr);          // uniform per warp
            float4 k4 = __ldg((const float4*)(g_xk + (size_t)row * CDIM) + lane);
            int g = lane ^ (sr & 7);
            *(float4*)&skv[sr * CDIM + g * 4] = k4;
        }
    }
    __syncthreads();

    const int s    = tid & 15;      // neighbor
    const int h    = tid >> 4;      // head
    const int base = h * DHEAD;
    const int qg   = lane >> 2;     // MMA groupID
    const int qtg  = lane & 3;      // MMA thread-in-group

    // --- positional encoding front-end (params via constant bank) ---
    const int nrow = sidx[s];
    float pr0 = p[nrow * 3 + 0] - p[i * 3 + 0];
    float pr1 = p[nrow * 3 + 1] - p[i * 3 + 1];
    float pr2 = p[nrow * 3 + 2] - p[i * 3 + 2];

    float t0 = pr0 * c_par.Wp1[0] + pr1 * c_par.Wp1[3] + pr2 * c_par.Wp1[6] + c_par.bp1[0];
    float t1 = pr0 * c_par.Wp1[1] + pr1 * c_par.Wp1[4] + pr2 * c_par.Wp1[7] + c_par.bp1[1];
    float t2 = pr0 * c_par.Wp1[2] + pr1 * c_par.Wp1[5] + pr2 * c_par.Wp1[8] + c_par.bp1[2];

    float m3 = (t0 + t1 + t2) * (1.f / 3.f);
    float d0 = t0 - m3, d1 = t1 - m3, d2 = t2 - m3;
    float v3 = (d0 * d0 + d1 * d1 + d2 * d2) * (1.f / 3.f);
    float rstd3 = rsqrtf(v3 + EPSV);
    float a0 = fmaxf(d0 * rstd3 * c_par.gp[0] + c_par.betap[0], 0.f);
    float a1 = fmaxf(d1 * rstd3 * c_par.gp[1] + c_par.betap[1], 0.f);
    float a2 = fmaxf(d2 * rstd3 * c_par.gp[2] + c_par.betap[2], 0.f);

    const u64 a0d = dup2(a0), a1d = dup2(a1), a2d = dup2(a2);
    const u64 neg1 = NEG1P;

    // --- r = k + pe - q (packed) ---
    u64 rp[8];
    const ulonglong2* xq2 = (const ulonglong2*)(g_xq + (size_t)i * CDIM + base);
#pragma unroll
    for (int j = 0; j < 4; j++) {
        int g = ((h << 2) + j) ^ (s & 7);
        ulonglong2 kk = *(const ulonglong2*)&skv[s * CDIM + g * 4];
        ulonglong2 w0 = *(const ulonglong2*)&c_par.Wp2[base + j * 4];
        ulonglong2 w1 = *(const ulonglong2*)&c_par.Wp2[128 + base + j * 4];
        ulonglong2 w2 = *(const ulonglong2*)&c_par.Wp2[256 + base + j * 4];
        ulonglong2 bb = *(const ulonglong2*)&c_par.bp2[base + j * 4];
        ulonglong2 qq = __ldg(xq2 + j);

        u64 pe0, pe1, tmp;
        F32X2_FMA(tmp, a2d, w2.x, bb.x);
        F32X2_FMA(tmp, a1d, w1.x, tmp);
        F32X2_FMA(pe0, a0d, w0.x, tmp);
        F32X2_FMA(tmp, a2d, w2.y, bb.y);
        F32X2_FMA(tmp, a1d, w1.y, tmp);
        F32X2_FMA(pe1, a0d, w0.y, tmp);

        u64 r0, r1;
        F32X2_ADD(r0, kk.x, pe0);
        F32X2_FMA(r0, qq.x, neg1, r0);
        F32X2_ADD(r1, kk.y, pe1);
        F32X2_FMA(r1, qq.y, neg1, r1);
        rp[j * 2 + 0] = r0;
        rp[j * 2 + 1] = r1;
    }

    // --- LN over D (packed stats) + relu, kept packed in rp ---
    {
        u64 sp = rp[0];
        F32X2_ADD(sp, sp, rp[1]); F32X2_ADD(sp, sp, rp[2]); F32X2_ADD(sp, sp, rp[3]);
        F32X2_ADD(sp, sp, rp[4]); F32X2_ADD(sp, sp, rp[5]); F32X2_ADD(sp, sp, rp[6]);
        F32X2_ADD(sp, sp, rp[7]);
        float2 sf = unpack2(sp);
        float mean = (sf.x + sf.y) * (1.f / DHEAD);
        u64 meanp = dup2(mean);
        u64 vp = 0ULL;
#pragma unroll
        for (int j = 0; j < 8; j++) {
            u64 dd;
            F32X2_FMA(dd, meanp, neg1, rp[j]);   // dd = r - mean
            F32X2_FMA(vp, dd, dd, vp);
            rp[j] = dd;
        }
        float2 vf = unpack2(vp);
        float rstd = rsqrtf((vf.x + vf.y) * (1.f / DHEAD) + EPSV);
        u64 rstdp = dup2(rstd);
        const u64* gwp = (const u64*)c_par.gw1;
        const u64* bwp = (const u64*)c_par.betaw1;
#pragma unroll
        for (int j = 0; j < 8; j++) {
            u64 rg, t;
            F32X2_MUL(rg, rstdp, gwp[j]);
            F32X2_FMA(t, rp[j], rg, bwp[j]);
            rp[j] = relu2(t);
        }
    }

    // --- w1 = r @ Ww1 via 8x mma.sync.m16n8k8.tf32 per warp ---
    u64 w1p[8];
    {
        float* rrow = srw + (tid & 96) * 20 + lane * 20;   // (warp*32 + lane)*20
        {
            ulonglong2 s0, s1, s2, s3;
            s0.x = rp[0]; s0.y = rp[1];
            s1.x = rp[2]; s1.y = rp[3];
            s2.x = rp[4]; s2.y = rp[5];
            s3.x = rp[6]; s3.y = rp[7];
            *(ulonglong2*)(rrow + 0)  = s0;
            *(ulonglong2*)(rrow + 4)  = s1;
            *(ulonglong2*)(rrow + 8)  = s2;
            *(ulonglong2*)(rrow + 12) = s3;
        }
        __syncwarp();

        // B fragments (Ww1 from smem; raw fp32 bits -> HW truncates to tf32)
        uint32_t bf[2][2][2];
#pragma unroll
        for (int kc = 0; kc < 2; kc++)
#pragma unroll
            for (int nc = 0; nc < 2; nc++) {
                bf[kc][nc][0] = __float_as_uint(sW1s[(kc * 8 + qtg)     * 17 + nc * 8 + qg]);
                bf[kc][nc][1] = __float_as_uint(sW1s[(kc * 8 + qtg + 4) * 17 + nc * 8 + qg]);
            }

        float cf[2][2][4];
#pragma unroll
        for (int mc = 0; mc < 2; mc++)
#pragma unroll
            for (int nc = 0; nc < 2; nc++)
#pragma unroll
                for (int q = 0; q < 4; q++) cf[mc][nc][q] = 0.f;

        const float* wb = srw + (tid & 96) * 20;
#pragma unroll
        for (int mc = 0; mc < 2; mc++) {
#pragma unroll
            for (int kc = 0; kc < 2; kc++) {
                uint32_t af[4];
                const float* ab = wb + (mc * 16 + qg) * 20 + kc * 8 + qtg;
                af[0] = __float_as_uint(ab[0]);
                af[1] = __float_as_uint(ab[8 * 20]);
                af[2] = __float_as_uint(ab[4]);
                af[3] = __float_as_uint(ab[8 * 20 + 4]);
                MMA_TF32(cf[mc][0], af, bf[kc][0]);
                MMA_TF32(cf[mc][1], af, bf[kc][1]);
            }
        }

        // write C fragments back into the same buffer (rows reused)
#pragma unroll
        for (int mc = 0; mc < 2; mc++)
#pragma unroll
            for (int nc = 0; nc < 2; nc++) {
                float* c0 = (float*)wb + (mc * 16 + qg) * 20 + nc * 8 + 2 * qtg;
                *(float2*)c0 = make_float2(cf[mc][nc][0], cf[mc][nc][1]);
                *(float2*)(c0 + 8 * 20) = make_float2(cf[mc][nc][2], cf[mc][nc][3]);
            }
        __syncwarp();

        // read back this lane's 16 outputs + bias
        ulonglong2 l0 = *(const ulonglong2*)(rrow + 0);
        ulonglong2 l1 = *(const ulonglong2*)(rrow + 4);
        ulonglong2 l2 = *(const ulonglong2*)(rrow + 8);
        ulonglong2 l3 = *(const ulonglong2*)(rrow + 12);
        const u64* bw = (const u64*)c_par.bw1;
        F32X2_ADD(w1p[0], l0.x, bw[0]);
        F32X2_ADD(w1p[1], l0.y, bw[1]);
        F32X2_ADD(w1p[2], l1.x, bw[2]);
        F32X2_ADD(w1p[3], l1.y, bw[3]);
        F32X2_ADD(w1p[4], l2.x, bw[4]);
        F32X2_ADD(w1p[5], l2.y, bw[5]);
        F32X2_ADD(w1p[6], l3.x, bw[6]);
        F32X2_ADD(w1p[7], l3.y, bw[7]);
    }

    // --- LN over OS (packed), relu ---
    {
        u64 sp = w1p[0];
        F32X2_ADD(sp, sp, w1p[1]); F32X2_ADD(sp, sp, w1p[2]); F32X2_ADD(sp, sp, w1p[3]);
        F32X2_ADD(sp, sp, w1p[4]); F32X2_ADD(sp, sp, w1p[5]); F32X2_ADD(sp, sp, w1p[6]);
        F32X2_ADD(sp, sp, w1p[7]);
        float2 sf = unpack2(sp);
        float mean = (sf.x + sf.y) * (1.f / OSDIM);
        u64 meanp = dup2(mean);
        u64 vp = 0ULL;
#pragma unroll
        for (int j = 0; j < 8; j++) {
            u64 dd;
            F32X2_FMA(dd, meanp, neg1, w1p[j]);
            F32X2_FMA(vp, dd, dd, vp);
            w1p[j] = dd;
        }
        float2 vf = unpack2(vp);
        float rstd = rsqrtf((vf.x + vf.y) * (1.f / OSDIM) + EPSV);
        u64 rstdp = dup2(rstd);
        const u64* gwp = (const u64*)c_par.gw2;
        const u64* bwp = (const u64*)c_par.betaw2;
#pragma unroll
        for (int j = 0; j < 8; j++) {
            u64 rg, t;
            F32X2_MUL(rg, rstdp, gwp[j]);
            F32X2_FMA(t, w1p[j], rg, bwp[j]);
            w1p[j] = relu2(t);
        }
    }

    // --- logit = (y @ rowsum(Ww2) + sum(bw2)) / 16 ---
    float logit;
    {
        const u64* rsp = (const u64*)c_par.rs2;
        u64 acc = 0ULL;
#pragma unroll
        for (int j = 0; j < 8; j++) F32X2_FMA(acc, w1p[j], rsp[j], acc);
        float2 af = unpack2(acc);
        logit = (af.x + af.y + c_par.bw2sum) * (1.f / OSDIM);
    }

    // --- prefetch V column (channel tid of each neighbor row) ---
    float vv[SNBR];
#pragma unroll
    for (int t = 0; t < SNBR; t++) {
        int row = sidx[t];
        vv[t] = __ldg(g_xv + (size_t)row * CDIM + tid);
    }

    // --- softmax over s (16-lane butterfly) ---
    float mx = logit;
#pragma unroll
    for (int j = 8; j >= 1; j >>= 1)
        mx = fmaxf(mx, __shfl_xor_sync(0xffffffffu, mx, j));
    float e = __expf(logit - mx);
    float se = e;
#pragma unroll
    for (int j = 8; j >= 1; j >>= 1)
        se += __shfl_xor_sync(0xffffffffu, se, j);
    float w = __fdividef(e, se);

    // --- abar_t = sum_s w[h,s] * a_t[s] ---
    float wa0 = w * a0, wa1 = w * a1, wa2 = w * a2;
#pragma unroll
    for (int j = 8; j >= 1; j >>= 1) {
        wa0 += __shfl_xor_sync(0xffffffffu, wa0, j);
        wa1 += __shfl_xor_sync(0xffffffffu, wa1, j);
        wa2 += __shfl_xor_sync(0xffffffffu, wa2, j);
    }

    // --- V term: out_c = sum_s w[h,s]*xv[row_s][c]; weights via shfl ---
    float acc = 0.f;
#pragma unroll
    for (int t = 0; t < SNBR; t++) {
        float wt = __shfl_sync(0xffffffffu, w, (lane & 16) | t);
        acc = fmaf(wt, vv[t], acc);
    }

    // --- folded pe term: abar @ Wp2[:,c] + bp2[c] ---
    float peo = __ldg(bp2g + tid);
    peo = fmaf(wa2, __ldg(Wp2g + 256 + tid), peo);
    peo = fmaf(wa1, __ldg(Wp2g + 128 + tid), peo);
    peo = fmaf(wa0, __ldg(Wp2g + tid),       peo);

    out[(size_t)i * CDIM + tid] = acc + peo;
}

// ---------------------------------------------------------------------------
// Launch: R15 fork/join topology (proven).
// ---------------------------------------------------------------------------
extern "C" void kernel_launch(void* const* d_in, const int* in_sizes, int n_in,
                              void* d_out, int out_size)
{
    const float* p      = (const float*)d_in[0];
    const float* x      = (const float*)d_in[1];
    const int*   idx    = (const int*)  d_in[2];
    const float* Wq     = (const float*)d_in[3];
    const float* bq     = (const float*)d_in[4];
    const float* Wk     = (const float*)d_in[5];
    const float* bk     = (const float*)d_in[6];
    const float* Wv     = (const float*)d_in[7];
    const float* bv     = (const float*)d_in[8];
    const float* Wp1    = (const float*)d_in[9];
    const float* bp1    = (const float*)d_in[10];
    const float* gp     = (const float*)d_in[11];
    const float* betap  = (const float*)d_in[12];
    const float* Wp2    = (const float*)d_in[13];
    const float* bp2    = (const float*)d_in[14];
    const float* gw1    = (const float*)d_in[15];
    const float* betaw1 = (const float*)d_in[16];
    const float* Ww1    = (const float*)d_in[17];
    const float* bw1    = (const float*)d_in[18];
    const float* gw2    = (const float*)d_in[19];
    const float* betaw2 = (const float*)d_in[20];
    const float* Ww2    = (const float*)d_in[21];
    const float* bw2    = (const float*)d_in[22];
    float* out = (float*)d_out;

    static cudaStream_t s2 = nullptr;
    static cudaEvent_t evFork, evG0, evC, evA;
    if (!s2) {
        cudaStreamCreateWithFlags(&s2, cudaStreamNonBlocking);
        cudaEventCreateWithFlags(&evFork, cudaEventDisableTiming);
        cudaEventCreateWithFlags(&evG0, cudaEventDisableTiming);
        cudaEventCreateWithFlags(&evC, cudaEventDisableTiming);
        cudaEventCreateWithFlags(&evA, cudaEventDisableTiming);
        cudaFuncSetAttribute(qkv_gemm_tf32,
                             cudaFuncAttributeMaxDynamicSharedMemorySize,
                             GEMM_SMEM_BYTES);
    }

    // Fork s2 from the (captured) default stream.
    cudaEventRecord(evFork, 0);
    cudaStreamWaitEvent(s2, evFork, 0);

    // s2: GEMM half0 -> GEMM half1.
    dim3 ggrid((NHALF + GTM - 1) / GTM, CDIM / GTN, 3);
    qkv_gemm_tf32<<<ggrid, 256, GEMM_SMEM_BYTES, s2>>>(
        x, Wq, bq, Wk, bk, Wv, bv, 0, NHALF);
    cudaEventRecord(evG0, s2);
    qkv_gemm_tf32<<<ggrid, 256, GEMM_SMEM_BYTES, s2>>>(
        x, Wq, bq, Wk, bk, Wv, bv, NHALF, NPTS);

    // default: stage params + copy to constant bank (overlaps gemm half0).
    stage_kernel<<<1, 384>>>(Wp1, bp1, gp, betap, Wp2, bp2,
                             gw1, betaw1, Ww1, bw1, gw2, betaw2, Ww2, bw2);
    void* stage_addr = nullptr;
    cudaGetSymbolAddress(&stage_addr, g_stage);
    cudaMemcpyToSymbolAsync(c_par, stage_addr, sizeof(CParams), 0,
                            cudaMemcpyDeviceToDevice, 0);
    cudaEventRecord(evC, 0);

    // s2: attn half1 right after gemm half1 (in-stream dep), after c_par copy.
    cudaStreamWaitEvent(s2, evC, 0);
    attn_kernel<<<NHALF, 128, 0, s2>>>(p, idx, Ww1, Wp2, bp2, out, NHALF);
    cudaEventRecord(evA, s2);

    // default: attn half0 (needs gemm half0); overlaps gemm half1 + attn half1.
    cudaStreamWaitEvent(0, evG0, 0);
    attn_kernel<<<NHALF, 128>>>(p, idx, Ww1, Wp2, bp2, out, 0);

    // Join s2 back into the capture stream.
    cudaStreamWaitEvent(0, evA, 0);
}

// round 17
// speedup vs baseline: 1.1444x; 1.1444x over previous
#include <cuda_runtime.h>
#include <cstdint>

#define NPTS 30000
#define NHALF 15000
#define CDIM 128
#define HEADS 8
#define DHEAD 16
#define SNBR 16
#define OSDIM 16
#define EPSV 1e-5f

typedef unsigned long long u64;

// packed f32x2 helpers (FFMA2 path — PTX-only on sm_103a)
#define F32X2_FMA(d, a, b, c) \
    asm("fma.rn.f32x2 %0, %1, %2, %3;" : "=l"(d) : "l"(a), "l"(b), "l"(c))
#define F32X2_ADD(d, a, b) \
    asm("add.rn.f32x2 %0, %1, %2;" : "=l"(d) : "l"(a), "l"(b))
#define F32X2_MUL(d, a, b) \
    asm("mul.rn.f32x2 %0, %1, %2;" : "=l"(d) : "l"(a), "l"(b))

__device__ __forceinline__ u64 pack2(float lo, float hi) {
    u64 r; asm("mov.b64 %0, {%1, %2};" : "=l"(r) : "f"(lo), "f"(hi)); return r;
}
__device__ __forceinline__ u64 dup2(float x) {
    u64 r; asm("mov.b64 %0, {%1, %1};" : "=l"(r) : "f"(x)); return r;
}
__device__ __forceinline__ float2 unpack2(u64 v) {
    float lo, hi; asm("mov.b64 {%0, %1}, %2;" : "=f"(lo), "=f"(hi) : "l"(v));
    return make_float2(lo, hi);
}
__device__ __forceinline__ u64 relu2(u64 x) {
    float2 f = unpack2(x);
    return pack2(fmaxf(f.x, 0.f), fmaxf(f.y, 0.f));
}

#define NEG1P 0xBF800000BF800000ULL   // (-1.0f, -1.0f)

// tf32 helpers
__device__ __forceinline__ uint32_t f2tf(float f) {
    uint32_t r; asm("cvt.rna.tf32.f32 %0, %1;" : "=r"(r) : "f"(f)); return r;
}
#define MMA_TF32(c, a, b) \
    asm("mma.sync.aligned.m16n8k8.row.col.f32.tf32.tf32.f32 " \
        "{%0,%1,%2,%3}, {%4,%5,%6,%7}, {%8,%9}, {%0,%1,%2,%3};" \
        : "+f"((c)[0]), "+f"((c)[1]), "+f"((c)[2]), "+f"((c)[3]) \
        : "r"((a)[0]), "r"((a)[1]), "r"((a)[2]), "r"((a)[3]), \
          "r"((b)[0]), "r"((b)[1]))

// ---------------------------------------------------------------------------
// Block-invariant parameters in the constant bank (R13/R15 layout — proven).
// ---------------------------------------------------------------------------
struct __align__(16) CParams {
    float Ww1[DHEAD * OSDIM];   // 256
    float Wp2[3 * CDIM];        // 384
    float bp2[CDIM];            // 128
    float gw1[DHEAD];
    float betaw1[DHEAD];
    float bw1[OSDIM];
    float gw2[OSDIM];
    float betaw2[OSDIM];
    float rs2[OSDIM];           // rowsum(Ww2)
    float Wp1[9], bp1[3], gp[3], betap[3];
    float bw2sum;               // sum(bw2)
};

__constant__ CParams c_par;
__device__   CParams g_stage;

// Scratch (device globals: no allocation allowed)
__device__ __align__(256) float g_xq[NPTS * CDIM];
__device__ __align__(256) float g_xk[NPTS * CDIM];
__device__ __align__(256) float g_xv[NPTS * CDIM];

// ---------------------------------------------------------------------------
// Kernel 0: pack block-invariant params into g_stage (then D2D -> c_par).
// ---------------------------------------------------------------------------
__global__ void stage_kernel(const float* __restrict__ Wp1, const float* __restrict__ bp1,
                             const float* __restrict__ gp,  const float* __restrict__ betap,
                             const float* __restrict__ Wp2, const float* __restrict__ bp2,
                             const float* __restrict__ gw1, const float* __restrict__ betaw1,
                             const float* __restrict__ Ww1, const float* __restrict__ bw1,
                             const float* __restrict__ gw2, const float* __restrict__ betaw2,
                             const float* __restrict__ Ww2, const float* __restrict__ bw2)
{
    int t = threadIdx.x;   // 384 threads
    if (t < 384) g_stage.Wp2[t] = Wp2[t];
    if (t < 256) g_stage.Ww1[t] = Ww1[t];
    if (t < 128) g_stage.bp2[t] = bp2[t];
    if (t < 16) {
        g_stage.gw1[t]    = gw1[t];
        g_stage.betaw1[t] = betaw1[t];
        g_stage.bw1[t]    = bw1[t];
        g_stage.gw2[t]    = gw2[t];
        g_stage.betaw2[t] = betaw2[t];
        float rs = 0.f;
#pragma unroll
        for (int o = 0; o < OSDIM; o++) rs += Ww2[t * OSDIM + o];
        g_stage.rs2[t] = rs;
    }
    if (t < 9) g_stage.Wp1[t] = Wp1[t];
    if (t < 3) {
        g_stage.bp1[t]   = bp1[t];
        g_stage.gp[t]    = gp[t];
        g_stage.betap[t] = betap[t];
    }
    if (t == 0) {
        float sb = 0.f;
#pragma unroll
        for (int o = 0; o < OSDIM; o++) sb += bw2[o];
        g_stage.bw2sum = sb;
    }
}

// ---------------------------------------------------------------------------
// Kernel 1: fused QKV GEMM on tensor cores — single-pass TF32 (proven).
// ---------------------------------------------------------------------------
#define GTM 128
#define GTN 64
#define GTK 32
#define AS_STR 36
#define BS_STR 72
#define GEMM_SMEM_WORDS (GTM * AS_STR + GTK * BS_STR)
#define GEMM_SMEM_BYTES (GEMM_SMEM_WORDS * 4)

__global__ __launch_bounds__(256, 2)
void qkv_gemm_tf32(const float* __restrict__ x,
                   const float* __restrict__ Wq, const float* __restrict__ bq,
                   const float* __restrict__ Wk, const float* __restrict__ bk,
                   const float* __restrict__ Wv, const float* __restrict__ bv,
                   int row_base, int row_end)
{
    const float* W; const float* bias; float* dst;
    if (blockIdx.z == 0)      { W = Wq; bias = bq; dst = g_xq; }
    else if (blockIdx.z == 1) { W = Wk; bias = bk; dst = g_xk; }
    else                      { W = Wv; bias = bv; dst = g_xv; }

    extern __shared__ uint32_t smem_u[];
    uint32_t* As = smem_u;
    uint32_t* Bs = As + GTM * AS_STR;

    const int tid  = threadIdx.x;
    const int wid  = tid >> 5;
    const int lane = tid & 31;
    const int g    = lane >> 2;
    const int tg   = lane & 3;

    const int warp_m = wid & 3;
    const int warp_n = wid >> 2;
    const int row0 = row_base + blockIdx.x * GTM;
    const int col0 = blockIdx.y * GTN;

    float c[2][4][4];
#pragma unroll
    for (int mt = 0; mt < 2; mt++)
#pragma unroll
        for (int nt = 0; nt < 4; nt++)
#pragma unroll
            for (int q = 0; q < 4; q++) c[mt][nt][q] = 0.f;

    const int arow_ = tid >> 3;
    const int ak4   = (tid & 7) * 4;
    const int brow_ = tid >> 4;
    const int bn4   = (tid & 15) * 4;

    for (int kk = 0; kk < CDIM; kk += GTK) {
        __syncthreads();

#pragma unroll
        for (int ps = 0; ps < 4; ps++) {
            int m  = arow_ + ps * 32;
            int gr = row0 + m;
            float4 v = (gr < row_end)
                     ? *(const float4*)(x + (size_t)gr * CDIM + kk + ak4)
                     : make_float4(0.f, 0.f, 0.f, 0.f);
            uint4 hi;
            hi.x = f2tf(v.x); hi.y = f2tf(v.y);
            hi.z = f2tf(v.z); hi.w = f2tf(v.w);
            *(uint4*)&As[m * AS_STR + ak4] = hi;
        }
#pragma unroll
        for (int ps = 0; ps < 2; ps++) {
            int k = brow_ + ps * 16;
            float4 v = *(const float4*)(W + (size_t)(kk + k) * CDIM + col0 + bn4);
            uint4 hi;
            hi.x = f2tf(v.x); hi.y = f2tf(v.y);
            hi.z = f2tf(v.z); hi.w = f2tf(v.w);
            *(uint4*)&Bs[k * BS_STR + bn4] = hi;
        }
        __syncthreads();

#pragma unroll
        for (int ks = 0; ks < 4; ks++) {
            const int k0 = ks * 8;
            uint32_t ah[2][4], bh[4][2];
#pragma unroll
            for (int mt = 0; mt < 2; mt++) {
                int rb = warp_m * 32 + mt * 16 + g;
                int o  = rb * AS_STR + k0 + tg;
                ah[mt][0] = As[o];
                ah[mt][1] = As[o + 8 * AS_STR];
                ah[mt][2] = As[o + 4];
                ah[mt][3] = As[o + 8 * AS_STR + 4];
            }
#pragma unroll
            for (int nt = 0; nt < 4; nt++) {
                int cb = warp_n * 32 + nt * 8 + g;
                int o  = (k0 + tg) * BS_STR + cb;
                bh[nt][0] = Bs[o];
                bh[nt][1] = Bs[o + 4 * BS_STR];
            }
#pragma unroll
            for (int mt = 0; mt < 2; mt++)
#pragma unroll
                for (int nt = 0; nt < 4; nt++)
                    MMA_TF32(c[mt][nt], ah[mt], bh[nt]);
        }
    }

#pragma unroll
    for (int nt = 0; nt < 4; nt++) {
        int cn = col0 + warp_n * 32 + nt * 8 + 2 * tg;
        float2 bb = *(const float2*)(bias + cn);
#pragma unroll
        for (int mt = 0; mt < 2; mt++) {
            int gr0 = row0 + warp_m * 32 + mt * 16 + g;
            if (gr0 < row_end) {
                float2 o0 = make_float2(c[mt][nt][0] + bb.x, c[mt][nt][1] + bb.y);
                *(float2*)(dst + (size_t)gr0 * CDIM + cn) = o0;
            }
            int gr1 = gr0 + 8;
            if (gr1 < row_end) {
                float2 o1 = make_float2(c[mt][nt][2] + bb.x, c[mt][nt][3] + bb.y);
                *(float2*)(dst + (size_t)gr1 * CDIM + cn) = o1;
            }
        }
    }
}

// ---------------------------------------------------------------------------
// Kernel 2: per-point fused attention — R15 structure (proven), with serial
// dependency chains broken up: tree-reduced LN means, dual-accumulator
// variances / logit / V-term. Same instruction mix, ~120 fewer exposed
// latency cycles per thread.
// ---------------------------------------------------------------------------
__global__ __launch_bounds__(128)
void attn_kernel(const float* __restrict__ p,
                 const int*   __restrict__ idx,
                 const float* __restrict__ Wp2g,
                 const float* __restrict__ bp2g,
                 float* __restrict__ out,
                 int off)
{
    const int i   = blockIdx.x + off;
    const int tid = threadIdx.x;          // 0..127
    const int lane = tid & 31;

    __shared__ __align__(16) float skv[SNBR * CDIM];   // K only, swizzled
    __shared__ int sidx[SNBR];

    if (tid < SNBR) sidx[tid] = idx[i * SNBR + tid];

    // --- gather K rows: warp-uniform row index via LDG, swizzled STS ---
    {
        const int warp = tid >> 5;
#pragma unroll
        for (int j = 0; j < 4; j++) {
            int sr  = warp * 4 + j;
            int row = __ldg(idx + i * SNBR + sr);          // uniform per warp
            float4 k4 = __ldg((const float4*)(g_xk + (size_t)row * CDIM) + lane);
            int g = lane ^ (sr & 7);
            *(float4*)&skv[sr * CDIM + g * 4] = k4;
        }
    }
    __syncthreads();

    const int s    = tid & 15;      // neighbor
    const int h    = tid >> 4;      // head
    const int base = h * DHEAD;

    // --- positional encoding front-end (params via constant bank) ---
    const int nrow = sidx[s];
    float pr0 = p[nrow * 3 + 0] - p[i * 3 + 0];
    float pr1 = p[nrow * 3 + 1] - p[i * 3 + 1];
    float pr2 = p[nrow * 3 + 2] - p[i * 3 + 2];

    float t0 = pr0 * c_par.Wp1[0] + pr1 * c_par.Wp1[3] + pr2 * c_par.Wp1[6] + c_par.bp1[0];
    float t1 = pr0 * c_par.Wp1[1] + pr1 * c_par.Wp1[4] + pr2 * c_par.Wp1[7] + c_par.bp1[1];
    float t2 = pr0 * c_par.Wp1[2] + pr1 * c_par.Wp1[5] + pr2 * c_par.Wp1[8] + c_par.bp1[2];

    float m3 = (t0 + t1 + t2) * (1.f / 3.f);
    float d0 = t0 - m3, d1 = t1 - m3, d2 = t2 - m3;
    float v3 = (d0 * d0 + d1 * d1 + d2 * d2) * (1.f / 3.f);
    float rstd3 = rsqrtf(v3 + EPSV);
    float a0 = fmaxf(d0 * rstd3 * c_par.gp[0] + c_par.betap[0], 0.f);
    float a1 = fmaxf(d1 * rstd3 * c_par.gp[1] + c_par.betap[1], 0.f);
    float a2 = fmaxf(d2 * rstd3 * c_par.gp[2] + c_par.betap[2], 0.f);

    const u64 a0d = dup2(a0), a1d = dup2(a1), a2d = dup2(a2);
    const u64 neg1 = NEG1P;

    // --- r = k + pe - q (packed) ---
    u64 rp[8];
    const ulonglong2* xq2 = (const ulonglong2*)(g_xq + (size_t)i * CDIM + base);
#pragma unroll
    for (int j = 0; j < 4; j++) {
        int g = ((h << 2) + j) ^ (s & 7);
        ulonglong2 kk = *(const ulonglong2*)&skv[s * CDIM + g * 4];
        ulonglong2 w0 = *(const ulonglong2*)&c_par.Wp2[base + j * 4];
        ulonglong2 w1 = *(const ulonglong2*)&c_par.Wp2[128 + base + j * 4];
        ulonglong2 w2 = *(const ulonglong2*)&c_par.Wp2[256 + base + j * 4];
        ulonglong2 bb = *(const ulonglong2*)&c_par.bp2[base + j * 4];
        ulonglong2 qq = __ldg(xq2 + j);

        u64 pe0, pe1, tmp;
        F32X2_FMA(tmp, a2d, w2.x, bb.x);
        F32X2_FMA(tmp, a1d, w1.x, tmp);
        F32X2_FMA(pe0, a0d, w0.x, tmp);
        F32X2_FMA(tmp, a2d, w2.y, bb.y);
        F32X2_FMA(tmp, a1d, w1.y, tmp);
        F32X2_FMA(pe1, a0d, w0.y, tmp);

        u64 r0, r1;
        F32X2_ADD(r0, kk.x, pe0);
        F32X2_FMA(r0, qq.x, neg1, r0);
        F32X2_ADD(r1, kk.y, pe1);
        F32X2_FMA(r1, qq.y, neg1, r1);
        rp[j * 2 + 0] = r0;
        rp[j * 2 + 1] = r1;
    }

    // --- LN over D: tree-reduced mean, dual-accumulator variance ---
    float r[DHEAD];
    {
        u64 s01, s23, s45, s67, sA, sB, sp;
        F32X2_ADD(s01, rp[0], rp[1]);
        F32X2_ADD(s23, rp[2], rp[3]);
        F32X2_ADD(s45, rp[4], rp[5]);
        F32X2_ADD(s67, rp[6], rp[7]);
        F32X2_ADD(sA, s01, s23);
        F32X2_ADD(sB, s45, s67);
        F32X2_ADD(sp, sA, sB);
        float2 sf = unpack2(sp);
        float mean = (sf.x + sf.y) * (1.f / DHEAD);
        u64 meanp = dup2(mean);
        u64 vp0 = 0ULL, vp1 = 0ULL;
#pragma unroll
        for (int j = 0; j < 8; j += 2) {
            u64 dd0, dd1;
            F32X2_FMA(dd0, meanp, neg1, rp[j]);       // dd = r - mean
            F32X2_FMA(dd1, meanp, neg1, rp[j + 1]);
            F32X2_FMA(vp0, dd0, dd0, vp0);
            F32X2_FMA(vp1, dd1, dd1, vp1);
            rp[j]     = dd0;
            rp[j + 1] = dd1;
        }
        u64 vp;
        F32X2_ADD(vp, vp0, vp1);
        float2 vf = unpack2(vp);
        float rstd = rsqrtf((vf.x + vf.y) * (1.f / DHEAD) + EPSV);
        u64 rstdp = dup2(rstd);
        const u64* gwp = (const u64*)c_par.gw1;
        const u64* bwp = (const u64*)c_par.betaw1;
#pragma unroll
        for (int j = 0; j < 8; j++) {
            u64 rg, t;
            F32X2_MUL(rg, rstdp, gwp[j]);
            F32X2_FMA(t, rp[j], rg, bwp[j]);
            float2 tf = unpack2(t);
            r[2 * j + 0] = fmaxf(tf.x, 0.f);
            r[2 * j + 1] = fmaxf(tf.y, 0.f);
        }
    }

    // --- w1 = relu_ln(r) @ Ww1 + bw1 (weights via constant port; 8
    //     independent accumulator chains interleave — already ILP-rich) ---
    u64 w1p[8];
    {
        const u64* bw = (const u64*)c_par.bw1;
#pragma unroll
        for (int j = 0; j < 8; j++) w1p[j] = bw[j];
#pragma unroll
        for (int d = 0; d < DHEAD; d++) {
            u64 ud = dup2(r[d]);
            const ulonglong2* wr = (const ulonglong2*)&c_par.Ww1[d * OSDIM];
            ulonglong2 wa = wr[0], wb = wr[1], wc = wr[2], wd_ = wr[3];
            F32X2_FMA(w1p[0], ud, wa.x, w1p[0]);
            F32X2_FMA(w1p[1], ud, wa.y, w1p[1]);
            F32X2_FMA(w1p[2], ud, wb.x, w1p[2]);
            F32X2_FMA(w1p[3], ud, wb.y, w1p[3]);
            F32X2_FMA(w1p[4], ud, wc.x, w1p[4]);
            F32X2_FMA(w1p[5], ud, wc.y, w1p[5]);
            F32X2_FMA(w1p[6], ud, wd_.x, w1p[6]);
            F32X2_FMA(w1p[7], ud, wd_.y, w1p[7]);
        }
    }

    // --- LN over OS: tree-reduced mean, dual-accumulator variance ---
    {
        u64 s01, s23, s45, s67, sA, sB, sp;
        F32X2_ADD(s01, w1p[0], w1p[1]);
        F32X2_ADD(s23, w1p[2], w1p[3]);
        F32X2_ADD(s45, w1p[4], w1p[5]);
        F32X2_ADD(s67, w1p[6], w1p[7]);
        F32X2_ADD(sA, s01, s23);
        F32X2_ADD(sB, s45, s67);
        F32X2_ADD(sp, sA, sB);
        float2 sf = unpack2(sp);
        float mean = (sf.x + sf.y) * (1.f / OSDIM);
        u64 meanp = dup2(mean);
        u64 vp0 = 0ULL, vp1 = 0ULL;
#pragma unroll
        for (int j = 0; j < 8; j += 2) {
            u64 dd0, dd1;
            F32X2_FMA(dd0, meanp, neg1, w1p[j]);
            F32X2_FMA(dd1, meanp, neg1, w1p[j + 1]);
            F32X2_FMA(vp0, dd0, dd0, vp0);
            F32X2_FMA(vp1, dd1, dd1, vp1);
            w1p[j]     = dd0;
            w1p[j + 1] = dd1;
        }
        u64 vp;
        F32X2_ADD(vp, vp0, vp1);
        float2 vf = unpack2(vp);
        float rstd = rsqrtf((vf.x + vf.y) * (1.f / OSDIM) + EPSV);
        u64 rstdp = dup2(rstd);
        const u64* gwp = (const u64*)c_par.gw2;
        const u64* bwp = (const u64*)c_par.betaw2;
#pragma unroll
        for (int j = 0; j < 8; j++) {
            u64 rg, t;
            F32X2_MUL(rg, rstdp, gwp[j]);
            F32X2_FMA(t, w1p[j], rg, bwp[j]);
            w1p[j] = relu2(t);
        }
    }

    // --- logit = (y @ rowsum(Ww2) + sum(bw2)) / 16 (dual accumulators) ---
    float logit;
    {
        const u64* rsp = (const u64*)c_par.rs2;
        u64 acc0 = 0ULL, acc1 = 0ULL;
#pragma unroll
        for (int j = 0; j < 8; j += 2) {
            F32X2_FMA(acc0, w1p[j],     rsp[j],     acc0);
            F32X2_FMA(acc1, w1p[j + 1], rsp[j + 1], acc1);
        }
        u64 acc;
        F32X2_ADD(acc, acc0, acc1);
        float2 af = unpack2(acc);
        logit = (af.x + af.y + c_par.bw2sum) * (1.f / OSDIM);
    }

    // --- prefetch V column (channel tid of each neighbor row) ---
    float vv[SNBR];
#pragma unroll
    for (int t = 0; t < SNBR; t++) {
        int row = sidx[t];
        vv[t] = __ldg(g_xv + (size_t)row * CDIM + tid);
    }

    // --- softmax over s (16-lane butterfly) ---
    float mx = logit;
#pragma unroll
    for (int j = 8; j >= 1; j >>= 1)
        mx = fmaxf(mx, __shfl_xor_sync(0xffffffffu, mx, j));
    float e = __expf(logit - mx);
    float se = e;
#pragma unroll
    for (int j = 8; j >= 1; j >>= 1)
        se += __shfl_xor_sync(0xffffffffu, se, j);
    float w = __fdividef(e, se);

    // --- abar_t = sum_s w[h,s] * a_t[s] (3 independent chains interleave) ---
    float wa0 = w * a0, wa1 = w * a1, wa2 = w * a2;
#pragma unroll
    for (int j = 8; j >= 1; j >>= 1) {
        wa0 += __shfl_xor_sync(0xffffffffu, wa0, j);
        wa1 += __shfl_xor_sync(0xffffffffu, wa1, j);
        wa2 += __shfl_xor_sync(0xffffffffu, wa2, j);
    }

    // --- V term: dual-accumulator FMA chain, weights via shfl ---
    float acc0 = 0.f, acc1 = 0.f;
#pragma unroll
    for (int t = 0; t < SNBR; t += 2) {
        float wt0 = __shfl_sync(0xffffffffu, w, (lane & 16) | t);
        float wt1 = __shfl_sync(0xffffffffu, w, (lane & 16) | (t + 1));
        acc0 = fmaf(wt0, vv[t],     acc0);
        acc1 = fmaf(wt1, vv[t + 1], acc1);
    }
    float acc = acc0 + acc1;

    // --- folded pe term: abar @ Wp2[:,c] + bp2[c] ---
    float peo = __ldg(bp2g + tid);
    peo = fmaf(wa2, __ldg(Wp2g + 256 + tid), peo);
    peo = fmaf(wa1, __ldg(Wp2g + 128 + tid), peo);
    peo = fmaf(wa0, __ldg(Wp2g + tid),       peo);

    out[(size_t)i * CDIM + tid] = acc + peo;
}

// ---------------------------------------------------------------------------
// Launch: R15 fork/join topology (proven).
// ---------------------------------------------------------------------------
extern "C" void kernel_launch(void* const* d_in, const int* in_sizes, int n_in,
                              void* d_out, int out_size)
{
    const float* p      = (const float*)d_in[0];
    const float* x      = (const float*)d_in[1];
    const int*   idx    = (const int*)  d_in[2];
    const float* Wq     = (const float*)d_in[3];
    const float* bq     = (const float*)d_in[4];
    const float* Wk     = (const float*)d_in[5];
    const float* bk     = (const float*)d_in[6];
    const float* Wv     = (const float*)d_in[7];
    const float* bv     = (const float*)d_in[8];
    const float* Wp1    = (const float*)d_in[9];
    const float* bp1    = (const float*)d_in[10];
    const float* gp     = (const float*)d_in[11];
    const float* betap  = (const float*)d_in[12];
    const float* Wp2    = (const float*)d_in[13];
    const float* bp2    = (const float*)d_in[14];
    const float* gw1    = (const float*)d_in[15];
    const float* betaw1 = (const float*)d_in[16];
    const float* Ww1    = (const float*)d_in[17];
    const float* bw1    = (const float*)d_in[18];
    const float* gw2    = (const float*)d_in[19];
    const float* betaw2 = (const float*)d_in[20];
    const float* Ww2    = (const float*)d_in[21];
    const float* bw2    = (const float*)d_in[22];
    float* out = (float*)d_out;

    static cudaStream_t s2 = nullptr;
    static cudaEvent_t evFork, evG0, evC, evA;
    if (!s2) {
        cudaStreamCreateWithFlags(&s2, cudaStreamNonBlocking);
        cudaEventCreateWithFlags(&evFork, cudaEventDisableTiming);
        cudaEventCreateWithFlags(&evG0, cudaEventDisableTiming);
        cudaEventCreateWithFlags(&evC, cudaEventDisableTiming);
        cudaEventCreateWithFlags(&evA, cudaEventDisableTiming);
        cudaFuncSetAttribute(qkv_gemm_tf32,
                             cudaFuncAttributeMaxDynamicSharedMemorySize,
                             GEMM_SMEM_BYTES);
    }

    // Fork s2 from the (captured) default stream.
    cudaEventRecord(evFork, 0);
    cudaStreamWaitEvent(s2, evFork, 0);

    // s2: GEMM half0 -> GEMM half1.
    dim3 ggrid((NHALF + GTM - 1) / GTM, CDIM / GTN, 3);
    qkv_gemm_tf32<<<ggrid, 256, GEMM_SMEM_BYTES, s2>>>(
        x, Wq, bq, Wk, bk, Wv, bv, 0, NHALF);
    cudaEventRecord(evG0, s2);
    qkv_gemm_tf32<<<ggrid, 256, GEMM_SMEM_BYTES, s2>>>(
        x, Wq, bq, Wk, bk, Wv, bv, NHALF, NPTS);

    // default: stage params + copy to constant bank (overlaps gemm half0).
    stage_kernel<<<1, 384>>>(Wp1, bp1, gp, betap, Wp2, bp2,
                             gw1, betaw1, Ww1, bw1, gw2, betaw2, Ww2, bw2);
    void* stage_addr = nullptr;
    cudaGetSymbolAddress(&stage_addr, g_stage);
    cudaMemcpyToSymbolAsync(c_par, stage_addr, sizeof(CParams), 0,
                            cudaMemcpyDeviceToDevice, 0);
    cudaEventRecord(evC, 0);

    // s2: attn half1 right after gemm half1 (in-stream dep), after c_par copy.
    cudaStreamWaitEvent(s2, evC, 0);
    attn_kernel<<<NHALF, 128, 0, s2>>>(p, idx, Wp2, bp2, out, NHALF);
    cudaEventRecord(evA, s2);

    // default: attn half0 (needs gemm half0); overlaps gemm half1 + attn half1.
    cudaStreamWaitEvent(0, evG0, 0);
    attn_kernel<<<NHALF, 128>>>(p, idx, Wp2, bp2, out, 0);

    // Join s2 back into the capture stream.
    cudaStreamWaitEvent(0, evA, 0);
}